// round 9
// baseline (speedup 1.0000x reference)
#include <cuda_runtime.h>
#include <cstdint>
#include <math.h>

#define NB      4
#define NGRID   512
#define NTARGET 1024
#define NBASIS  5
#define NCH     8

#define NCHUNK  8                 // grid chunks per CTA (one per warp quad)
#define CHUNK   (NGRID / NCHUNK)  // 64 grid points
#define TILES   64                // 16-target tiles per batch
#define ROWF2   (NGRID + 2)       // padded row stride (float2) -> conflict-free
#define STG     (4 * NBASIS * NCH + 8)  // 168: staged h floats per warp (+pad)

// ---------------------------------------------------------------------------
// Single kernel, no cross-CTA traffic. CTA = 1024 threads = 32 warps,
// one CTA per (batch, 16-target tile), grid = 256.
// Fill: per-warp coalesced LDG -> smem stage -> conflict-free fold (fixes the
// 10-lines-per-LDG wavefront blowup seen in R8's profile).
// Main: warp w = (chunk w>>2, channel pair w&3), 1 target/thread.
// ---------------------------------------------------------------------------
__global__ void __launch_bounds__(1024)
finallayer_big(const float* __restrict__ x_grid,    // [NB][NGRID][NCH]
               const float* __restrict__ h_grid,    // [NB][NGRID][NBASIS][NCH]
               const float* __restrict__ target_x,  // [NB][NTARGET][NCH]
               const float* __restrict__ sigma,     // [NBASIS][NCH]
               const float* __restrict__ g_w,       // [1][NBASIS]
               const float* __restrict__ g_b,       // [1]
               float* __restrict__ out)             // [NB][NTARGET][NCH]
{
    __shared__ __align__(16) float2 pairs[NCH * ROWF2];  // (x*sc0, hsum0) ~32 KB
    __shared__ float s_stage[32][STG];                   // h transpose stage ~21.5 KB
    __shared__ float s_part[NCHUNK][16 * NCH];           // chunk partials, 4 KB
    __shared__ float s_sc[NCH][NBASIS];
    __shared__ int   s_grp[NCH][NBASIS];
    __shared__ int   s_nu[NCH];
    __shared__ float s_gw[NBASIS];

    const int tid  = threadIdx.x;
    const int tile = blockIdx.x & (TILES - 1);
    const int b    = blockIdx.x >> 6;

    // --- per-channel scale dedup (redundant per CTA, trivial) ---
    if (tid < NCH) {
        const float C = 0.8493218002880190f;  // sqrt(0.5 * log2(e))
        float s[NBASIS], uniq[NBASIS];
        int nu = 0;
#pragma unroll
        for (int k = 0; k < NBASIS; ++k)
            s[k] = expf(sigma[k * NCH + tid]) + 1e-6f;
#pragma unroll
        for (int k = 0; k < NBASIS; ++k) {
            int u = -1;
            for (int j = 0; j < nu; ++j)
                if (uniq[j] == s[k]) { u = j; break; }
            if (u < 0) { u = nu; uniq[nu++] = s[k]; }
            s_grp[tid][k] = u;
        }
        s_nu[tid] = nu;
        for (int u = 0; u < nu; ++u) s_sc[tid][u] = C / uniq[u];
    } else if (tid < NCH + NBASIS) {
        s_gw[tid - NCH] = g_w[tid - NCH];
    }
    __syncthreads();

    const int w    = tid >> 5;
    const int lane = tid & 31;

    // --- coalesced fill: warp w owns grid points [w*16, w*16+16) ---
    const float* xg = x_grid + b * (NGRID * NCH);
    const float* hg = h_grid + b * (NGRID * NBASIS * NCH);
    {
        const int cf = lane & 7;          // channel this lane folds
        const int gp = lane >> 3;         // local grid point 0..3
        const float sc0 = s_sc[cf][0];
#pragma unroll
        for (int blk = 0; blk < 4; ++blk) {
            const int g0 = w * 16 + blk * 4;              // 4 grid points
            const float* hb = hg + g0 * (NBASIS * NCH);   // 160 contiguous floats
#pragma unroll
            for (int j = 0; j < 5; ++j)                   // coalesced, 1 line/LDG
                s_stage[w][lane + 32 * j] = hb[lane + 32 * j];
            __syncwarp();
            float acc = 0.f;
#pragma unroll
            for (int k = 0; k < NBASIS; ++k)              // conflict-free LDS
                if (s_grp[cf][k] == 0)
                    acc += s_stage[w][gp * (NBASIS * NCH) + k * NCH + cf] * s_gw[k];
            float xv = xg[g0 * NCH + lane];               // coalesced
            pairs[cf * ROWF2 + g0 + gp] = make_float2(xv * sc0, acc);
            __syncwarp();
        }
    }
    __syncthreads();

    // --- main loop: warp = (chunk, channel pair); 1 target/thread ---
    const int chunk = w >> 2;
    const int c     = ((w & 3) << 1) | (lane >> 4);
    const int tl    = lane & 15;                 // local target 0..15
    const int t     = tile * 16 + tl;

    const float tv = __ldg(&target_x[(b * NTARGET + t) * NCH + c]);
    const float ts = tv * s_sc[c][0];
    float acc = 0.f;

    const float4* pc = (const float4*)(pairs + c * ROWF2) + chunk * (CHUNK / 2);
#pragma unroll 8
    for (int gg = 0; gg < CHUNK / 2; ++gg) {
        float4 q = pc[gg];                       // (x0*sc, h0, x1*sc, h1)
        float d0 = q.x - ts;
        float d1 = q.z - ts;
        float a0 = -d0 * d0;
        float a1 = -d1 * d1;
        float w0, w1;
        asm("ex2.approx.ftz.f32 %0, %1;" : "=f"(w0) : "f"(a0));
        asm("ex2.approx.ftz.f32 %0, %1;" : "=f"(w1) : "f"(a1));
        acc = fmaf(w0, q.y, acc);
        acc = fmaf(w1, q.w, acc);
    }

    // --- generic cold path: extra unique scales (not taken for uniform sigma) ---
    const int nu = s_nu[c];
    const int gc0 = chunk * CHUNK;
    for (int u = 1; u < nu; ++u) {
        const float sc  = s_sc[c][u];
        const float nts = -tv * sc;
        for (int g = 0; g < CHUNK; ++g) {
            float xv = __ldg(&xg[(gc0 + g) * NCH + c]);
            float hv = 0.f;
#pragma unroll
            for (int k = 0; k < NBASIS; ++k)
                if (s_grp[c][k] == u)
                    hv += __ldg(&hg[((gc0 + g) * NBASIS + k) * NCH + c]) * s_gw[k];
            float ds = fmaf(xv, sc, nts);
            float a  = -ds * ds;
            float wv;
            asm("ex2.approx.ftz.f32 %0, %1;" : "=f"(wv) : "f"(a));
            acc = fmaf(wv, hv, acc);
        }
    }

    // --- intra-CTA reduction over the 8 chunks ---
    s_part[chunk][tl * NCH + c] = acc;
    __syncthreads();

    if (tid < 16 * NCH) {                        // tid = t_local*8 + c
        float sum = __ldg(g_b);
#pragma unroll
        for (int s = 0; s < NCHUNK; ++s)         // fixed order -> deterministic
            sum += s_part[s][tid];
        out[(b * NTARGET + tile * 16) * NCH + tid] = sum;  // coalesced
    }
}

// ---------------------------------------------------------------------------
extern "C" void kernel_launch(void* const* d_in, const int* in_sizes, int n_in,
                              void* d_out, int out_size) {
    const float* x_grid   = (const float*)d_in[0];  // [4,512,8]
    const float* h_grid   = (const float*)d_in[1];  // [4,512,5,8]
    const float* target_x = (const float*)d_in[2];  // [4,1024,8]
    const float* sigma    = (const float*)d_in[3];  // [5,8]
    const float* g_w      = (const float*)d_in[4];  // [1,5]
    const float* g_b      = (const float*)d_in[5];  // [1]
    float* out = (float*)d_out;                     // [4,1024,8]

    finallayer_big<<<NB * TILES, 1024>>>(
        x_grid, h_grid, target_x, sigma, g_w, g_b, out);
}